// round 1
// baseline (speedup 1.0000x reference)
#include <cuda_runtime.h>
#include <math.h>

#define BATCH 2048
#define SEQ   80
#define EMBED 100
#define UNITS 512
#define VOCAB 10000

// Scratch (device globals — no allocation allowed):
// g_T = emb @ Wx0 + b0  (layer-0 x-projection lookup table), 20.5 MB
__device__ float g_T[VOCAB * UNITS];
// Ping-pong hidden states for the 3 layers, 25.2 MB
__device__ float g_state[3][2][BATCH * UNITS];

// ---------------------------------------------------------------------------
// Kernel 1: precompute T[w][n] = sum_e emb[w][e] * Wx0[e][n] + b0[n]
// M=10000, K=100, N=512.  BM=BN=64, BK=20, 256 threads, 4x4 per thread.
// ---------------------------------------------------------------------------
__global__ void __launch_bounds__(256)
xproj_kernel(const float* __restrict__ emb,
             const float* __restrict__ Wx0,
             const float* __restrict__ b0)
{
    __shared__ float As[20][68];  // [k][m]
    __shared__ float Bs[20][68];  // [k][n]

    const int m0  = blockIdx.x * 64;
    const int n0  = blockIdx.y * 64;
    const int tid = threadIdx.x;
    const int tx  = tid & 15;   // n
    const int ty  = tid >> 4;   // m

    float acc[4][4] = {};

    for (int k0 = 0; k0 < EMBED; k0 += 20) {
        for (int i = tid; i < 64 * 20; i += 256) {
            int m = i / 20, k = i % 20;
            int gm = m0 + m;
            As[k][m] = (gm < VOCAB) ? emb[gm * EMBED + k0 + k] : 0.0f;
        }
        for (int i = tid; i < 20 * 64; i += 256) {
            int k = i / 64, n = i % 64;
            Bs[k][n] = Wx0[(k0 + k) * UNITS + n0 + n];
        }
        __syncthreads();
        #pragma unroll
        for (int kk = 0; kk < 20; ++kk) {
            float a[4], b[4];
            #pragma unroll
            for (int i = 0; i < 4; ++i) a[i] = As[kk][ty * 4 + i];
            #pragma unroll
            for (int j = 0; j < 4; ++j) b[j] = Bs[kk][tx * 4 + j];
            #pragma unroll
            for (int i = 0; i < 4; ++i)
                #pragma unroll
                for (int j = 0; j < 4; ++j)
                    acc[i][j] = fmaf(a[i], b[j], acc[i][j]);
        }
        __syncthreads();
    }

    #pragma unroll
    for (int i = 0; i < 4; ++i) {
        int row = m0 + ty * 4 + i;
        if (row >= VOCAB) continue;
        #pragma unroll
        for (int j = 0; j < 4; ++j) {
            int col = n0 + tx * 4 + j;
            g_T[row * UNITS + col] = acc[i][j] + b0[col];
        }
    }
}

// ---------------------------------------------------------------------------
// Kernel 2: zero the phase-0 state buffers
// ---------------------------------------------------------------------------
__global__ void zero_states()
{
    int i = blockIdx.x * blockDim.x + threadIdx.x;
    g_state[0][0][i] = 0.0f;
    g_state[1][0][i] = 0.0f;
    g_state[2][0][i] = 0.0f;
}

__device__ __forceinline__ float fast_tanh(float x)
{
    // tanh(x) = 1 - 2/(exp(2x)+1); __expf overflow/underflow gives correct +-1.
    float e = __expf(2.0f * x);
    return 1.0f - __fdividef(2.0f, e + 1.0f);
}

// ---------------------------------------------------------------------------
// Kernel 3: one (timestep, layer) step.
//   layer 0 : sout = tanh( T[tokens[b,t]] + sin @ Wh )        (b0 folded in T)
//   layer1/2: sout = tanh( xin @ Wx + sin @ Wh + bias )       (xin = prev layer out)
// GEMM tile: BM=128, BN=64, BK=16, 256 threads, 8x4 per thread.
// Grid: (UNITS/64, BATCH/128) = (8, 16) = 128 blocks.
// ---------------------------------------------------------------------------
__global__ void __launch_bounds__(256)
step_kernel(const float* __restrict__ Wx,
            const float* __restrict__ Wh,
            const float* __restrict__ bias,
            const int*   __restrict__ tokens,
            int t, int layer, int phase)
{
    const float* sin  = g_state[layer][phase];
    float*       sout = g_state[layer][phase ^ 1];
    const float* xin  = (layer == 0) ? nullptr : g_state[layer - 1][phase ^ 1];

    const int m0  = blockIdx.y * 128;
    const int n0  = blockIdx.x * 64;
    const int tid = threadIdx.x;
    const int tx  = tid & 15;   // n: 16 lanes * 4 cols
    const int ty  = tid >> 4;   // m: 16 groups * 8 rows

    __shared__ float As[16][132];  // [k][m], padded
    __shared__ float Bs[16][68];   // [k][n], padded

    float acc[8][4] = {};

    // load indices
    const int lr = tid >> 2;          // 0..63 (A tile row)
    const int lc = (tid & 3) << 2;    // 0,4,8,12 (A tile k)
    const int wr = tid >> 4;          // 0..15 (W tile k)
    const int wc = (tid & 15) << 2;   // 0..60 (W tile n)

    #pragma unroll
    for (int mat = 0; mat < 2; ++mat) {
        const float* A = mat ? sin : xin;
        const float* W = mat ? Wh  : Wx;
        if (A == nullptr) continue;

        for (int k0 = 0; k0 < UNITS; k0 += 16) {
            float4 a0 = *(const float4*)&A[(size_t)(m0 + lr)      * UNITS + k0 + lc];
            float4 a1 = *(const float4*)&A[(size_t)(m0 + lr + 64) * UNITS + k0 + lc];
            As[lc + 0][lr]      = a0.x;
            As[lc + 1][lr]      = a0.y;
            As[lc + 2][lr]      = a0.z;
            As[lc + 3][lr]      = a0.w;
            As[lc + 0][lr + 64] = a1.x;
            As[lc + 1][lr + 64] = a1.y;
            As[lc + 2][lr + 64] = a1.z;
            As[lc + 3][lr + 64] = a1.w;
            *(float4*)&Bs[wr][wc] = *(const float4*)&W[(size_t)(k0 + wr) * UNITS + n0 + wc];
            __syncthreads();

            #pragma unroll
            for (int kk = 0; kk < 16; ++kk) {
                float a[8], b[4];
                *(float4*)&a[0] = *(const float4*)&As[kk][ty * 8];
                *(float4*)&a[4] = *(const float4*)&As[kk][ty * 8 + 4];
                *(float4*)&b[0] = *(const float4*)&Bs[kk][tx * 4];
                #pragma unroll
                for (int i = 0; i < 8; ++i)
                    #pragma unroll
                    for (int j = 0; j < 4; ++j)
                        acc[i][j] = fmaf(a[i], b[j], acc[i][j]);
            }
            __syncthreads();
        }
    }

    // epilogue: (+bias) (+T gather for layer 0), tanh, store
    #pragma unroll
    for (int i = 0; i < 8; ++i) {
        const int row = m0 + ty * 8 + i;
        const float* Trow = nullptr;
        if (layer == 0) {
            int w = tokens[(size_t)row * SEQ + t];
            Trow = &g_T[(size_t)w * UNITS];
        }
        #pragma unroll
        for (int j = 0; j < 4; ++j) {
            const int col = n0 + tx * 4 + j;
            float v = acc[i][j];
            if (bias) v += bias[col];
            if (Trow) v += Trow[col];
            sout[(size_t)row * UNITS + col] = fast_tanh(v);
        }
    }
}

// ---------------------------------------------------------------------------
// Kernel 4: head — out[b] = sigmoid( s2[b,:] . Wout + bout )
// ---------------------------------------------------------------------------
__global__ void __launch_bounds__(256)
head_kernel(const float* __restrict__ Wout,
            const float* __restrict__ bout,
            float* __restrict__ out)
{
    const float* s2 = g_state[2][0];  // final state lands in phase 0 (SEQ even)
    int row  = blockIdx.x * 8 + (threadIdx.x >> 5);
    int lane = threadIdx.x & 31;

    const float* sr = &s2[(size_t)row * UNITS];
    float sum = 0.0f;
    #pragma unroll 4
    for (int k = lane; k < UNITS; k += 32)
        sum += sr[k] * Wout[k];
    #pragma unroll
    for (int o = 16; o; o >>= 1)
        sum += __shfl_xor_sync(0xFFFFFFFFu, sum, o);
    if (lane == 0) {
        float logit = sum + bout[0];
        out[row] = __fdividef(1.0f, 1.0f + __expf(-logit));
    }
}

// ---------------------------------------------------------------------------
extern "C" void kernel_launch(void* const* d_in, const int* in_sizes, int n_in,
                              void* d_out, int out_size)
{
    const int*   tokens = (const int*)  d_in[0];
    const float* emb    = (const float*)d_in[1];
    const float* Wx0    = (const float*)d_in[2];
    const float* Wh0    = (const float*)d_in[3];
    const float* b0     = (const float*)d_in[4];   (void)b0;  // folded into g_T
    const float* Wx1    = (const float*)d_in[5];
    const float* Wh1    = (const float*)d_in[6];
    const float* b1     = (const float*)d_in[7];
    const float* Wx2    = (const float*)d_in[8];
    const float* Wh2    = (const float*)d_in[9];
    const float* b2     = (const float*)d_in[10];
    const float* Wout   = (const float*)d_in[11];
    const float* bout   = (const float*)d_in[12];
    float* out = (float*)d_out;

    // 1) layer-0 x-projection table: T = emb @ Wx0 + b0
    xproj_kernel<<<dim3((VOCAB + 63) / 64, UNITS / 64), 256>>>(emb, d_in[2] ? (const float*)d_in[2] : Wx0, (const float*)d_in[4]);

    // 2) zero initial states
    zero_states<<<(BATCH * UNITS) / 256, 256>>>();

    // 3) 80 timesteps x 3 layers (kernel boundary = layer sync)
    dim3 grid(UNITS / 64, BATCH / 128);  // (8, 16)
    for (int t = 0; t < SEQ; ++t) {
        int p = t & 1;
        step_kernel<<<grid, 256>>>(nullptr, Wh0, nullptr, tokens, t, 0, p);
        step_kernel<<<grid, 256>>>(Wx1,     Wh1, b1,      tokens, t, 1, p);
        step_kernel<<<grid, 256>>>(Wx2,     Wh2, b2,      tokens, t, 2, p);
    }

    // 4) head
    head_kernel<<<BATCH / 8, 256>>>(Wout, bout, out);
}

// round 3
// speedup vs baseline: 3.0997x; 3.0997x over previous
#include <cuda_runtime.h>
#include <cuda_bf16.h>
#include <stdint.h>
#include <math.h>

#define BATCH 2048
#define SEQ   80
#define EMBED 100
#define UNITS 512
#define VOCAB 10000

// ---------------- device globals (no allocation allowed) ----------------
__device__ float g_T[VOCAB * UNITS];                   // emb@Wx0+b0 table (fp32)
__device__ __nv_bfloat16 g_s[3][2][2][BATCH * UNITS];  // [layer][phase][hi/lo] states
__device__ __nv_bfloat16 g_W[5][2][UNITS * UNITS];     // transposed split weights [n][k]:
                                                       // 0=Wh0 1=Wx1 2=Wh1 3=Wx2 4=Wh2

// ---------------- helpers ----------------
__device__ __forceinline__ uint32_t smem_u32(const void* p) {
    uint32_t a;
    asm("{ .reg .u64 t; cvta.to.shared.u64 t, %1; cvt.u32.u64 %0, t; }" : "=r"(a) : "l"(p));
    return a;
}

__device__ __forceinline__ uint32_t swz(uint32_t off) {
    return off ^ ((off >> 3) & 0x70);   // SW128: 8-row period, 16B granules
}

#define CP16(dst, src) \
    asm volatile("cp.async.cg.shared.global [%0], [%1], 16;" :: "r"(dst), "l"(src) : "memory")

__device__ __forceinline__ void ldsm4(uint32_t (&r)[4], uint32_t addr) {
    asm volatile("ldmatrix.sync.aligned.m8n8.x4.shared.b16 {%0,%1,%2,%3}, [%4];"
        : "=r"(r[0]), "=r"(r[1]), "=r"(r[2]), "=r"(r[3]) : "r"(addr));
}

__device__ __forceinline__ void mma16816(float (&d)[4], const uint32_t (&a)[4],
                                         const uint32_t* b) {
    asm volatile(
        "mma.sync.aligned.m16n8k16.row.col.f32.bf16.bf16.f32 "
        "{%0,%1,%2,%3}, {%4,%5,%6,%7}, {%8,%9}, {%0,%1,%2,%3};"
        : "+f"(d[0]), "+f"(d[1]), "+f"(d[2]), "+f"(d[3])
        : "r"(a[0]), "r"(a[1]), "r"(a[2]), "r"(a[3]), "r"(b[0]), "r"(b[1]));
}

__device__ __forceinline__ float fast_tanh(float x) {
    float e = __expf(2.0f * x);
    return 1.0f - __fdividef(2.0f, e + 1.0f);
}

__device__ __forceinline__ uint32_t pack_bf16(float x, float y) {
    __nv_bfloat16 hx = __float2bfloat16(x), hy = __float2bfloat16(y);
    return (uint32_t)__bfloat16_as_ushort(hx) | ((uint32_t)__bfloat16_as_ushort(hy) << 16);
}

// SMEM per stage: Ah 16K | Al 16K | Bh 8K | Bl 8K = 48K; 3 stages
#define STAGE 49152u
#define NSTAGE 3
#define SMEM_BYTES (NSTAGE * STAGE)

// ---------------------------------------------------------------------------
// xproj: g_T = emb @ Wx0 + b0   (fp32, M=10000 K=100 N=512, runs once per graph)
// ---------------------------------------------------------------------------
__global__ void __launch_bounds__(256)
xproj_kernel(const float* __restrict__ emb, const float* __restrict__ Wx0,
             const float* __restrict__ b0)
{
    __shared__ float As[20][68];
    __shared__ float Bs[20][68];
    const int m0 = blockIdx.x * 64, n0 = blockIdx.y * 64;
    const int tid = threadIdx.x, tx = tid & 15, ty = tid >> 4;
    float acc[4][4] = {};
    for (int k0 = 0; k0 < EMBED; k0 += 20) {
        for (int i = tid; i < 64 * 20; i += 256) {
            int m = i / 20, k = i % 20;
            int gm = m0 + m;
            As[k][m] = (gm < VOCAB) ? emb[gm * EMBED + k0 + k] : 0.0f;
        }
        for (int i = tid; i < 20 * 64; i += 256) {
            int k = i / 64, n = i % 64;
            Bs[k][n] = Wx0[(k0 + k) * UNITS + n0 + n];
        }
        __syncthreads();
        #pragma unroll
        for (int kk = 0; kk < 20; ++kk) {
            float a[4], b[4];
            #pragma unroll
            for (int i = 0; i < 4; ++i) a[i] = As[kk][ty * 4 + i];
            #pragma unroll
            for (int j = 0; j < 4; ++j) b[j] = Bs[kk][tx * 4 + j];
            #pragma unroll
            for (int i = 0; i < 4; ++i)
                #pragma unroll
                for (int j = 0; j < 4; ++j)
                    acc[i][j] = fmaf(a[i], b[j], acc[i][j]);
        }
        __syncthreads();
    }
    #pragma unroll
    for (int i = 0; i < 4; ++i) {
        int row = m0 + ty * 4 + i;
        if (row >= VOCAB) continue;
        #pragma unroll
        for (int j = 0; j < 4; ++j) {
            int col = n0 + tx * 4 + j;
            g_T[row * UNITS + col] = acc[i][j] + b0[col];
        }
    }
}

// ---------------------------------------------------------------------------
// split + transpose weights: g_W[m][hi/lo][n*512+k] = split(W[k*512+n])
// ---------------------------------------------------------------------------
__global__ void __launch_bounds__(256)
split_weights(const float* __restrict__ a0, const float* __restrict__ a1,
              const float* __restrict__ a2, const float* __restrict__ a3,
              const float* __restrict__ a4)
{
    int i = blockIdx.x * 256 + threadIdx.x;   // i = k*512+n
    int k = i >> 9, n = i & 511;
    const float* src[5] = {a0, a1, a2, a3, a4};
    #pragma unroll
    for (int m = 0; m < 5; ++m) {
        float v = src[m][i];
        __nv_bfloat16 h = __float2bfloat16(v);
        __nv_bfloat16 l = __float2bfloat16(v - __bfloat162float(h));
        g_W[m][0][n * UNITS + k] = h;
        g_W[m][1][n * UNITS + k] = l;
    }
}

__global__ void zero_states()
{
    int i = blockIdx.x * blockDim.x + threadIdx.x;
    __nv_bfloat16 z = __float2bfloat16(0.0f);
    #pragma unroll
    for (int l = 0; l < 3; ++l) {
        g_s[l][0][0][i] = z;
        g_s[l][0][1][i] = z;
    }
}

// ---------------------------------------------------------------------------
// chunk loader: A hi/lo (128 x 64) + B hi/lo (64 x 64) bf16, SW128 swizzled
// ---------------------------------------------------------------------------
__device__ __forceinline__ void load_chunk(uint32_t base,
    const __nv_bfloat16* __restrict__ Ah, const __nv_bfloat16* __restrict__ Al,
    const __nv_bfloat16* __restrict__ Bh, const __nv_bfloat16* __restrict__ Bl,
    int m0, int n0, int k0, int tid)
{
    #pragma unroll
    for (int i = 0; i < 4; ++i) {           // A: 1024 x 16B per plane
        int idx = tid + i * 256;
        int row = idx >> 3, g = idx & 7;
        uint32_t d = swz((uint32_t)(row * 128 + g * 16));
        size_t s = (size_t)(m0 + row) * UNITS + k0 + g * 8;
        CP16(base + d,          Ah + s);
        CP16(base + 16384 + d,  Al + s);
    }
    #pragma unroll
    for (int i = 0; i < 2; ++i) {           // B: 512 x 16B per plane
        int idx = tid + i * 256;
        int row = idx >> 3, g = idx & 7;
        uint32_t d = swz((uint32_t)(row * 128 + g * 16));
        size_t s = (size_t)(n0 + row) * UNITS + k0 + g * 8;
        CP16(base + 32768 + d,  Bh + s);
        CP16(base + 40960 + d,  Bl + s);
    }
    asm volatile("cp.async.commit_group;" ::: "memory");
}

// ---------------------------------------------------------------------------
// step kernel: one (t, layer).  C[128x64] per CTA, grid (8 N, 16 M) = 128 CTAs.
//   layer 0 : sout = tanh( T[token] + s @ Wh0 )
//   layer1/2: sout = tanh( x @ Wx + s @ Wh + bias )
// bf16x3 split via mma.sync m16n8k16, fp32 register accum.
// ---------------------------------------------------------------------------
__global__ void __launch_bounds__(256)
step_kernel(int layer, int phase, int t,
            const int* __restrict__ tokens, const float* __restrict__ bias)
{
    extern __shared__ __align__(1024) char smem[];
    const uint32_t sb = smem_u32(smem);
    const int tid = threadIdx.x, wid = tid >> 5, lane = tid & 31;
    const int n0 = blockIdx.x * 64, m0 = blockIdx.y * 128;

    const __nv_bfloat16 *Ah[2], *Al[2], *Bh[2], *Bl[2];
    int nmat;
    if (layer == 0) {
        nmat = 1;
        Ah[0] = g_s[0][phase][0];   Al[0] = g_s[0][phase][1];
        Bh[0] = g_W[0][0];          Bl[0] = g_W[0][1];
        Ah[1] = Ah[0]; Al[1] = Al[0]; Bh[1] = Bh[0]; Bl[1] = Bl[0];
    } else {
        nmat = 2;
        int wx = (layer == 1) ? 1 : 3;
        Ah[0] = g_s[layer - 1][phase ^ 1][0];  Al[0] = g_s[layer - 1][phase ^ 1][1];
        Bh[0] = g_W[wx][0];                    Bl[0] = g_W[wx][1];
        Ah[1] = g_s[layer][phase][0];          Al[1] = g_s[layer][phase][1];
        Bh[1] = g_W[wx + 1][0];                Bl[1] = g_W[wx + 1][1];
    }
    __nv_bfloat16* outh = g_s[layer][phase ^ 1][0];
    __nv_bfloat16* outl = g_s[layer][phase ^ 1][1];

    const int NC = nmat * 8;   // K-chunks of 64

    // warp layout: 4 m-warps x 2 n-warps; warp tile 32x32
    const int wm = (wid & 3) * 32;
    const int wn = (wid >> 2) * 32;

    // ldmatrix lane decode
    const int sel = lane >> 3, rowin = lane & 7;
    const int a_row  = wm + (sel & 1) * 8 + rowin;   // + mt*16
    const int a_colb = (sel >> 1) * 16;              // + ks*32
    const int b_row  = wn + (sel >> 1) * 8 + rowin;  // + bt*16
    const int b_colb = (sel & 1) * 16;               // + ks*32

    float acc[2][4][4] = {};

    // prologue: prime stages 0,1
    load_chunk(sb + 0 * STAGE, Ah[0], Al[0], Bh[0], Bl[0], m0, n0, 0, tid);
    load_chunk(sb + 1 * STAGE, Ah[1 >> 3], Al[1 >> 3], Bh[1 >> 3], Bl[1 >> 3],
               m0, n0, (1 & 7) * 64, tid);

    for (int c = 0; c < NC; ++c) {
        asm volatile("cp.async.wait_group 1;" ::: "memory");
        __syncthreads();

        const int nc = c + 2;
        if (nc < NC) {
            load_chunk(sb + (nc % NSTAGE) * STAGE,
                       Ah[nc >> 3], Al[nc >> 3], Bh[nc >> 3], Bl[nc >> 3],
                       m0, n0, (nc & 7) * 64, tid);
        } else {
            asm volatile("cp.async.commit_group;" ::: "memory");
        }

        const uint32_t Ah_b = sb + (uint32_t)(c % NSTAGE) * STAGE;
        const uint32_t Al_b = Ah_b + 16384;
        const uint32_t Bh_b = Ah_b + 32768;
        const uint32_t Bl_b = Ah_b + 40960;

        #pragma unroll
        for (int ks = 0; ks < 4; ++ks) {
            uint32_t ah[2][4], al[2][4], bh[2][4], bl[2][4];
            #pragma unroll
            for (int mt = 0; mt < 2; ++mt) {
                uint32_t off = swz((uint32_t)((a_row + mt * 16) * 128 + a_colb + ks * 32));
                ldsm4(ah[mt], Ah_b + off);
                ldsm4(al[mt], Al_b + off);
            }
            #pragma unroll
            for (int bt = 0; bt < 2; ++bt) {
                uint32_t off = swz((uint32_t)((b_row + bt * 16) * 128 + b_colb + ks * 32));
                ldsm4(bh[bt], Bh_b + off);
                ldsm4(bl[bt], Bl_b + off);
            }
            #pragma unroll
            for (int mt = 0; mt < 2; ++mt)
                #pragma unroll
                for (int j = 0; j < 4; ++j) {
                    const uint32_t* bhp = &bh[j >> 1][(j & 1) * 2];
                    const uint32_t* blp = &bl[j >> 1][(j & 1) * 2];
                    mma16816(acc[mt][j], ah[mt], bhp);   // hi*hi
                    mma16816(acc[mt][j], al[mt], bhp);   // lo*hi
                    mma16816(acc[mt][j], ah[mt], blp);   // hi*lo
                }
        }
    }

    // ---- epilogue: add T/bias, tanh, split hi/lo, packed stores ----
    const int grp = lane >> 2, qd = (lane & 3) * 2;
    #pragma unroll
    for (int mt = 0; mt < 2; ++mt) {
        const int r0 = m0 + wm + mt * 16 + grp;
        const int r1 = r0 + 8;
        const float *t0, *t1;
        if (layer == 0) {
            t0 = g_T + (size_t)tokens[(size_t)r0 * SEQ + t] * UNITS;
            t1 = g_T + (size_t)tokens[(size_t)r1 * SEQ + t] * UNITS;
        } else {
            t0 = bias; t1 = bias;
        }
        #pragma unroll
        for (int j = 0; j < 4; ++j) {
            const int c = n0 + wn + j * 8 + qd;
            float2 ad0 = *(const float2*)(t0 + c);
            float2 ad1 = *(const float2*)(t1 + c);
            float v00 = fast_tanh(acc[mt][j][0] + ad0.x);
            float v01 = fast_tanh(acc[mt][j][1] + ad0.y);
            float v10 = fast_tanh(acc[mt][j][2] + ad1.x);
            float v11 = fast_tanh(acc[mt][j][3] + ad1.y);

            float h00 = __bfloat162float(__float2bfloat16(v00));
            float h01 = __bfloat162float(__float2bfloat16(v01));
            float h10 = __bfloat162float(__float2bfloat16(v10));
            float h11 = __bfloat162float(__float2bfloat16(v11));

            *(uint32_t*)(outh + (size_t)r0 * UNITS + c) = pack_bf16(v00, v01);
            *(uint32_t*)(outl + (size_t)r0 * UNITS + c) = pack_bf16(v00 - h00, v01 - h01);
            *(uint32_t*)(outh + (size_t)r1 * UNITS + c) = pack_bf16(v10, v11);
            *(uint32_t*)(outl + (size_t)r1 * UNITS + c) = pack_bf16(v10 - h10, v11 - h11);
        }
    }
}

// ---------------------------------------------------------------------------
// head: out[b] = sigmoid( (s2_hi+s2_lo) . Wout + bout )
// ---------------------------------------------------------------------------
__global__ void __launch_bounds__(256)
head_kernel(const float* __restrict__ Wout, const float* __restrict__ bout,
            float* __restrict__ out)
{
    const __nv_bfloat16* sh = g_s[2][0][0];
    const __nv_bfloat16* sl = g_s[2][0][1];
    int row  = blockIdx.x * 8 + (threadIdx.x >> 5);
    int lane = threadIdx.x & 31;
    float sum = 0.0f;
    #pragma unroll 4
    for (int k = lane; k < UNITS; k += 32) {
        float v = __bfloat162float(sh[(size_t)row * UNITS + k]) +
                  __bfloat162float(sl[(size_t)row * UNITS + k]);
        sum += v * Wout[k];
    }
    #pragma unroll
    for (int o = 16; o; o >>= 1)
        sum += __shfl_xor_sync(0xFFFFFFFFu, sum, o);
    if (lane == 0) {
        float logit = sum + bout[0];
        out[row] = __fdividef(1.0f, 1.0f + __expf(-logit));
    }
}

// ---------------------------------------------------------------------------
extern "C" void kernel_launch(void* const* d_in, const int* in_sizes, int n_in,
                              void* d_out, int out_size)
{
    const int*   tokens = (const int*)  d_in[0];
    const float* emb    = (const float*)d_in[1];
    const float* Wx0    = (const float*)d_in[2];
    const float* Wh0    = (const float*)d_in[3];
    const float* b0     = (const float*)d_in[4];
    const float* Wx1    = (const float*)d_in[5];
    const float* Wh1    = (const float*)d_in[6];
    const float* b1     = (const float*)d_in[7];
    const float* Wx2    = (const float*)d_in[8];
    const float* Wh2    = (const float*)d_in[9];
    const float* b2     = (const float*)d_in[10];
    const float* Wout   = (const float*)d_in[11];
    const float* bout   = (const float*)d_in[12];
    float* out = (float*)d_out;

    cudaFuncSetAttribute(step_kernel, cudaFuncAttributeMaxDynamicSharedMemorySize,
                         SMEM_BYTES);

    // prologue
    xproj_kernel<<<dim3((VOCAB + 63) / 64, UNITS / 64), 256>>>(emb, Wx0, b0);
    split_weights<<<(UNITS * UNITS) / 256, 256>>>(Wh0, Wx1, Wh1, Wx2, Wh2);
    zero_states<<<(BATCH * UNITS) / 256, 256>>>();

    // 80 timesteps x 3 layers
    dim3 grid(UNITS / 64, BATCH / 128);   // (8 N-tiles, 16 M-tiles)
    for (int t = 0; t < SEQ; ++t) {
        int p = t & 1;
        step_kernel<<<grid, 256, SMEM_BYTES>>>(0, p, t, tokens, nullptr);
        step_kernel<<<grid, 256, SMEM_BYTES>>>(1, p, t, tokens, b1);
        step_kernel<<<grid, 256, SMEM_BYTES>>>(2, p, t, tokens, b2);
    }

    head_kernel<<<BATCH / 8, 256>>>(Wout, bout, out);
}

// round 4
// speedup vs baseline: 6.9905x; 2.2552x over previous
#include <cuda_runtime.h>
#include <cuda_fp16.h>
#include <stdint.h>
#include <math.h>

#define BATCH 2048
#define SEQ   80
#define EMBED 100
#define UNITS 512
#define VOCAB 10000

// ---------------- device globals (no allocation allowed) ----------------
__device__ float g_T[VOCAB * UNITS];            // emb@Wx0+b0 table (fp32, exact)
__device__ __half g_s[3][2][BATCH * UNITS];     // [layer][phase] fp16 states
__device__ __half g_W[5][UNITS * UNITS];        // transposed fp16 weights [n][k]:
                                                // 0=Wh0 1=Wx1 2=Wh1 3=Wx2 4=Wh2

// ---------------- helpers ----------------
__device__ __forceinline__ uint32_t smem_u32(const void* p) {
    uint32_t a;
    asm("{ .reg .u64 t; cvta.to.shared.u64 t, %1; cvt.u32.u64 %0, t; }" : "=r"(a) : "l"(p));
    return a;
}

__device__ __forceinline__ uint32_t swz(uint32_t off) {
    return off ^ ((off >> 3) & 0x70);   // SW128: 8-row period, 16B granules
}

#define CP16(dst, src) \
    asm volatile("cp.async.cg.shared.global [%0], [%1], 16;" :: "r"(dst), "l"(src) : "memory")

__device__ __forceinline__ void ldsm4(uint32_t (&r)[4], uint32_t addr) {
    asm volatile("ldmatrix.sync.aligned.m8n8.x4.shared.b16 {%0,%1,%2,%3}, [%4];"
        : "=r"(r[0]), "=r"(r[1]), "=r"(r[2]), "=r"(r[3]) : "r"(addr));
}

__device__ __forceinline__ void mma16816(float (&d)[4], const uint32_t (&a)[4],
                                         const uint32_t* b) {
    asm volatile(
        "mma.sync.aligned.m16n8k16.row.col.f32.f16.f16.f32 "
        "{%0,%1,%2,%3}, {%4,%5,%6,%7}, {%8,%9}, {%0,%1,%2,%3};"
        : "+f"(d[0]), "+f"(d[1]), "+f"(d[2]), "+f"(d[3])
        : "r"(a[0]), "r"(a[1]), "r"(a[2]), "r"(a[3]), "r"(b[0]), "r"(b[1]));
}

__device__ __forceinline__ float fast_tanh(float x) {
    float e = __expf(2.0f * x);
    return 1.0f - __fdividef(2.0f, e + 1.0f);
}

// Stage = one K-128 chunk: A(128x128) as two 16K halves + B(64x128) as two 8K halves
#define STAGE 49152u
#define NSTAGE 3
#define SMEM_BYTES (NSTAGE * STAGE)

// ---------------------------------------------------------------------------
// xproj: g_T = emb @ Wx0 + b0   (fp32, M=10000 K=100 N=512)
// ---------------------------------------------------------------------------
__global__ void __launch_bounds__(256)
xproj_kernel(const float* __restrict__ emb, const float* __restrict__ Wx0,
             const float* __restrict__ b0)
{
    __shared__ float As[20][68];
    __shared__ float Bs[20][68];
    const int m0 = blockIdx.x * 64, n0 = blockIdx.y * 64;
    const int tid = threadIdx.x, tx = tid & 15, ty = tid >> 4;
    float acc[4][4] = {};
    for (int k0 = 0; k0 < EMBED; k0 += 20) {
        for (int i = tid; i < 64 * 20; i += 256) {
            int m = i / 20, k = i % 20;
            int gm = m0 + m;
            As[k][m] = (gm < VOCAB) ? emb[gm * EMBED + k0 + k] : 0.0f;
        }
        for (int i = tid; i < 20 * 64; i += 256) {
            int k = i / 64, n = i % 64;
            Bs[k][n] = Wx0[(k0 + k) * UNITS + n0 + n];
        }
        __syncthreads();
        #pragma unroll
        for (int kk = 0; kk < 20; ++kk) {
            float a[4], b[4];
            #pragma unroll
            for (int i = 0; i < 4; ++i) a[i] = As[kk][ty * 4 + i];
            #pragma unroll
            for (int j = 0; j < 4; ++j) b[j] = Bs[kk][tx * 4 + j];
            #pragma unroll
            for (int i = 0; i < 4; ++i)
                #pragma unroll
                for (int j = 0; j < 4; ++j)
                    acc[i][j] = fmaf(a[i], b[j], acc[i][j]);
        }
        __syncthreads();
    }
    #pragma unroll
    for (int i = 0; i < 4; ++i) {
        int row = m0 + ty * 4 + i;
        if (row >= VOCAB) continue;
        #pragma unroll
        for (int j = 0; j < 4; ++j) {
            int col = n0 + tx * 4 + j;
            g_T[row * UNITS + col] = acc[i][j] + b0[col];
        }
    }
}

// ---------------------------------------------------------------------------
// transpose + convert weights: g_W[m][n*512+k] = fp16(W[k*512+n])
// ---------------------------------------------------------------------------
__global__ void __launch_bounds__(256)
conv_weights(const float* __restrict__ a0, const float* __restrict__ a1,
             const float* __restrict__ a2, const float* __restrict__ a3,
             const float* __restrict__ a4)
{
    int i = blockIdx.x * 256 + threadIdx.x;   // i = k*512+n
    int k = i >> 9, n = i & 511;
    const float* src[5] = {a0, a1, a2, a3, a4};
    #pragma unroll
    for (int m = 0; m < 5; ++m)
        g_W[m][n * UNITS + k] = __float2half_rn(src[m][i]);
}

__global__ void zero_states()
{
    int i = blockIdx.x * blockDim.x + threadIdx.x;
    const __half z = __float2half(0.0f);
    #pragma unroll
    for (int l = 0; l < 3; ++l)
        g_s[l][0][i] = z;
}

// ---------------------------------------------------------------------------
// stage loader: A (128 x 128) + B (64 x 128) fp16, stored as two 64-col halves,
// each half SW128-swizzled with 128B rows. One commit_group per stage.
// ---------------------------------------------------------------------------
__device__ __forceinline__ void load_stage(uint32_t base,
    const __half* __restrict__ A, const __half* __restrict__ B,
    int m0, int n0, int k0, int tid)
{
    #pragma unroll
    for (int h = 0; h < 2; ++h) {
        const int kh = k0 + h * 64;
        const uint32_t ab = base + h * 16384u;
        const uint32_t bb = base + 32768u + h * 8192u;
        #pragma unroll
        for (int i = 0; i < 4; ++i) {           // A half: 1024 x 16B
            int idx = tid + i * 256;
            int row = idx >> 3, g = idx & 7;
            uint32_t d = swz((uint32_t)(row * 128 + g * 16));
            CP16(ab + d, A + (size_t)(m0 + row) * UNITS + kh + g * 8);
        }
        #pragma unroll
        for (int i = 0; i < 2; ++i) {           // B half: 512 x 16B
            int idx = tid + i * 256;
            int row = idx >> 3, g = idx & 7;
            uint32_t d = swz((uint32_t)(row * 128 + g * 16));
            CP16(bb + d, B + (size_t)(n0 + row) * UNITS + kh + g * 8);
        }
    }
    asm volatile("cp.async.commit_group;" ::: "memory");
}

// ---------------------------------------------------------------------------
// step kernel: one (t, layer).  C[128x64] per CTA, grid (8 N, 16 M) = 128 CTAs.
//   layer 0 : sout = tanh( T[token] + s @ Wh0 )
//   layer1/2: sout = tanh( x @ Wx + s @ Wh + bias )
// fp16 mma.sync m16n8k16, fp32 register accum.
// ---------------------------------------------------------------------------
__global__ void __launch_bounds__(256)
step_kernel(int layer, int phase, int t,
            const int* __restrict__ tokens, const float* __restrict__ bias)
{
    extern __shared__ __align__(1024) char smem[];
    const uint32_t sb = smem_u32(smem);
    const int tid = threadIdx.x, wid = tid >> 5, lane = tid & 31;
    const int n0 = blockIdx.x * 64, m0 = blockIdx.y * 128;

    const __half *A[2], *B[2];
    int nmat;
    if (layer == 0) {
        nmat = 1;
        A[0] = g_s[0][phase];  B[0] = g_W[0];
        A[1] = A[0];           B[1] = B[0];
    } else {
        nmat = 2;
        int wx = (layer == 1) ? 1 : 3;
        A[0] = g_s[layer - 1][phase ^ 1];  B[0] = g_W[wx];
        A[1] = g_s[layer][phase];          B[1] = g_W[wx + 1];
    }
    __half* outp = g_s[layer][phase ^ 1];

    const int NC = nmat * 4;   // K-128 stages

    // warp layout: 4 m-warps x 2 n-warps; warp tile 32x32
    const int wm = (wid & 3) * 32;
    const int wn = (wid >> 2) * 32;

    // ldmatrix lane decode (within a 64-col swizzled half)
    const int sel = lane >> 3, rowin = lane & 7;
    const int a_row  = wm + (sel & 1) * 8 + rowin;   // + mt*16
    const int a_colb = (sel >> 1) * 16;              // + ks*32
    const int b_row  = wn + (sel >> 1) * 8 + rowin;  // + bt*16
    const int b_colb = (sel & 1) * 16;               // + ks*32

    float acc[2][4][4] = {};

    // prime stages 0,1
    load_stage(sb + 0 * STAGE, A[0], B[0], m0, n0, 0, tid);
    {
        int mt1 = (NC > 4) ? (1 >> 2) : 0;  // always 0
        load_stage(sb + 1 * STAGE, A[mt1], B[mt1], m0, n0, (1 & 3) * 128, tid);
    }

    for (int c = 0; c < NC; ++c) {
        asm volatile("cp.async.wait_group 1;" ::: "memory");
        __syncthreads();

        const int nc = c + 2;
        if (nc < NC) {
            load_stage(sb + (nc % NSTAGE) * STAGE,
                       A[nc >> 2], B[nc >> 2], m0, n0, (nc & 3) * 128, tid);
        } else {
            asm volatile("cp.async.commit_group;" ::: "memory");
        }

        const uint32_t stb = sb + (uint32_t)(c % NSTAGE) * STAGE;

        #pragma unroll
        for (int h = 0; h < 2; ++h) {
            const uint32_t Ab = stb + h * 16384u;
            const uint32_t Bb = stb + 32768u + h * 8192u;
            #pragma unroll
            for (int ks = 0; ks < 4; ++ks) {
                uint32_t a[2][4], b[2][4];
                #pragma unroll
                for (int mt = 0; mt < 2; ++mt) {
                    uint32_t off = swz((uint32_t)((a_row + mt * 16) * 128 + a_colb + ks * 32));
                    ldsm4(a[mt], Ab + off);
                }
                #pragma unroll
                for (int bt = 0; bt < 2; ++bt) {
                    uint32_t off = swz((uint32_t)((b_row + bt * 16) * 128 + b_colb + ks * 32));
                    ldsm4(b[bt], Bb + off);
                }
                #pragma unroll
                for (int mt = 0; mt < 2; ++mt)
                    #pragma unroll
                    for (int j = 0; j < 4; ++j)
                        mma16816(acc[mt][j], a[mt], &b[j >> 1][(j & 1) * 2]);
            }
        }
    }

    // ---- epilogue: add T/bias, tanh, fp16 store ----
    const int grp = lane >> 2, qd = (lane & 3) * 2;
    #pragma unroll
    for (int mt = 0; mt < 2; ++mt) {
        const int r0 = m0 + wm + mt * 16 + grp;
        const int r1 = r0 + 8;
        const float *t0, *t1;
        if (layer == 0) {
            t0 = g_T + (size_t)tokens[(size_t)r0 * SEQ + t] * UNITS;
            t1 = g_T + (size_t)tokens[(size_t)r1 * SEQ + t] * UNITS;
        } else {
            t0 = bias; t1 = bias;
        }
        #pragma unroll
        for (int j = 0; j < 4; ++j) {
            const int c = n0 + wn + j * 8 + qd;
            float2 ad0 = *(const float2*)(t0 + c);
            float2 ad1 = *(const float2*)(t1 + c);
            __half2 p0 = __floats2half2_rn(fast_tanh(acc[mt][j][0] + ad0.x),
                                           fast_tanh(acc[mt][j][1] + ad0.y));
            __half2 p1 = __floats2half2_rn(fast_tanh(acc[mt][j][2] + ad1.x),
                                           fast_tanh(acc[mt][j][3] + ad1.y));
            *reinterpret_cast<__half2*>(outp + (size_t)r0 * UNITS + c) = p0;
            *reinterpret_cast<__half2*>(outp + (size_t)r1 * UNITS + c) = p1;
        }
    }
}

// ---------------------------------------------------------------------------
// head: out[b] = sigmoid( s2[b,:] . Wout + bout )
// ---------------------------------------------------------------------------
__global__ void __launch_bounds__(256)
head_kernel(const float* __restrict__ Wout, const float* __restrict__ bout,
            float* __restrict__ out)
{
    const __half* s2 = g_s[2][0];   // SEQ even -> final state in phase 0
    int row  = blockIdx.x * 8 + (threadIdx.x >> 5);
    int lane = threadIdx.x & 31;
    float sum = 0.0f;
    #pragma unroll 4
    for (int k = lane; k < UNITS; k += 32)
        sum += __half2float(s2[(size_t)row * UNITS + k]) * Wout[k];
    #pragma unroll
    for (int o = 16; o; o >>= 1)
        sum += __shfl_xor_sync(0xFFFFFFFFu, sum, o);
    if (lane == 0) {
        float logit = sum + bout[0];
        out[row] = __fdividef(1.0f, 1.0f + __expf(-logit));
    }
}

// ---------------------------------------------------------------------------
extern "C" void kernel_launch(void* const* d_in, const int* in_sizes, int n_in,
                              void* d_out, int out_size)
{
    const int*   tokens = (const int*)  d_in[0];
    const float* emb    = (const float*)d_in[1];
    const float* Wx0    = (const float*)d_in[2];
    const float* Wh0    = (const float*)d_in[3];
    const float* b0     = (const float*)d_in[4];
    const float* Wx1    = (const float*)d_in[5];
    const float* Wh1    = (const float*)d_in[6];
    const float* b1     = (const float*)d_in[7];
    const float* Wx2    = (const float*)d_in[8];
    const float* Wh2    = (const float*)d_in[9];
    const float* b2     = (const float*)d_in[10];
    const float* Wout   = (const float*)d_in[11];
    const float* bout   = (const float*)d_in[12];
    float* out = (float*)d_out;

    cudaFuncSetAttribute(step_kernel, cudaFuncAttributeMaxDynamicSharedMemorySize,
                         SMEM_BYTES);

    // prologue
    xproj_kernel<<<dim3((VOCAB + 63) / 64, UNITS / 64), 256>>>(emb, Wx0, b0);
    conv_weights<<<(UNITS * UNITS) / 256, 256>>>(Wh0, Wx1, Wh1, Wx2, Wh2);
    zero_states<<<(BATCH * UNITS) / 256, 256>>>();

    // 80 timesteps x 3 layers
    dim3 grid(UNITS / 64, BATCH / 128);   // (8 N-tiles, 16 M-tiles)
    for (int t = 0; t < SEQ; ++t) {
        int p = t & 1;
        step_kernel<<<grid, 256, SMEM_BYTES>>>(0, p, t, tokens, nullptr);
        step_kernel<<<grid, 256, SMEM_BYTES>>>(1, p, t, tokens, b1);
        step_kernel<<<grid, 256, SMEM_BYTES>>>(2, p, t, tokens, b2);
    }

    head_kernel<<<BATCH / 8, 256>>>(Wout, bout, out);
}

// round 5
// speedup vs baseline: 7.1969x; 1.0295x over previous
#include <cuda_runtime.h>
#include <cuda_fp16.h>
#include <stdint.h>
#include <math.h>

#define BATCH 2048
#define SEQ   80
#define EMBED 100
#define UNITS 512
#define VOCAB 10000

// ---------------- device globals (no allocation allowed) ----------------
__device__ float g_T[VOCAB * UNITS];            // emb@Wx0+b0 table (fp32, exact)
__device__ __half g_s[3][2][BATCH * UNITS];     // [layer][phase] fp16 states
__device__ __half g_W[5][UNITS * UNITS];        // transposed fp16 weights [n][k]:
                                                // 0=Wh0 1=Wx1 2=Wh1 3=Wx2 4=Wh2
__device__ int g_bar[16];                       // per-m-group barrier counters

// ---------------- helpers ----------------
__device__ __forceinline__ uint32_t smem_u32(const void* p) {
    uint32_t a;
    asm("{ .reg .u64 t; cvta.to.shared.u64 t, %1; cvt.u32.u64 %0, t; }" : "=r"(a) : "l"(p));
    return a;
}

__device__ __forceinline__ uint32_t swz(uint32_t off) {
    return off ^ ((off >> 3) & 0x70);   // SW128: 8-row period, 16B granules
}

#define CP16(dst, src) \
    asm volatile("cp.async.cg.shared.global [%0], [%1], 16;" :: "r"(dst), "l"(src) : "memory")

__device__ __forceinline__ void ldsm4(uint32_t (&r)[4], uint32_t addr) {
    asm volatile("ldmatrix.sync.aligned.m8n8.x4.shared.b16 {%0,%1,%2,%3}, [%4];"
        : "=r"(r[0]), "=r"(r[1]), "=r"(r[2]), "=r"(r[3]) : "r"(addr));
}

__device__ __forceinline__ void mma16816(float (&d)[4], const uint32_t (&a)[4],
                                         const uint32_t* b) {
    asm volatile(
        "mma.sync.aligned.m16n8k16.row.col.f32.f16.f16.f32 "
        "{%0,%1,%2,%3}, {%4,%5,%6,%7}, {%8,%9}, {%0,%1,%2,%3};"
        : "+f"(d[0]), "+f"(d[1]), "+f"(d[2]), "+f"(d[3])
        : "r"(a[0]), "r"(a[1]), "r"(a[2]), "r"(a[3]), "r"(b[0]), "r"(b[1]));
}

__device__ __forceinline__ float fast_tanh(float x) {
    float e = __expf(2.0f * x);
    return 1.0f - __fdividef(2.0f, e + 1.0f);
}

// Stage = one K-128 chunk: A(128x128) two 16K halves + B(64x128) two 8K halves
#define STAGE 49152u
#define NSTAGE 3
#define SMEM_BYTES (NSTAGE * STAGE)

// ---------------------------------------------------------------------------
// xproj: g_T = emb @ Wx0 + b0   (fp32, M=10000 K=100 N=512)
// ---------------------------------------------------------------------------
__global__ void __launch_bounds__(256)
xproj_kernel(const float* __restrict__ emb, const float* __restrict__ Wx0,
             const float* __restrict__ b0)
{
    __shared__ float As[20][68];
    __shared__ float Bs[20][68];
    const int m0 = blockIdx.x * 64, n0 = blockIdx.y * 64;
    const int tid = threadIdx.x, tx = tid & 15, ty = tid >> 4;
    float acc[4][4] = {};
    for (int k0 = 0; k0 < EMBED; k0 += 20) {
        for (int i = tid; i < 64 * 20; i += 256) {
            int m = i / 20, k = i % 20;
            int gm = m0 + m;
            As[k][m] = (gm < VOCAB) ? emb[gm * EMBED + k0 + k] : 0.0f;
        }
        for (int i = tid; i < 20 * 64; i += 256) {
            int k = i / 64, n = i % 64;
            Bs[k][n] = Wx0[(k0 + k) * UNITS + n0 + n];
        }
        __syncthreads();
        #pragma unroll
        for (int kk = 0; kk < 20; ++kk) {
            float a[4], b[4];
            #pragma unroll
            for (int i = 0; i < 4; ++i) a[i] = As[kk][ty * 4 + i];
            #pragma unroll
            for (int j = 0; j < 4; ++j) b[j] = Bs[kk][tx * 4 + j];
            #pragma unroll
            for (int i = 0; i < 4; ++i)
                #pragma unroll
                for (int j = 0; j < 4; ++j)
                    acc[i][j] = fmaf(a[i], b[j], acc[i][j]);
        }
        __syncthreads();
    }
    #pragma unroll
    for (int i = 0; i < 4; ++i) {
        int row = m0 + ty * 4 + i;
        if (row >= VOCAB) continue;
        #pragma unroll
        for (int j = 0; j < 4; ++j) {
            int col = n0 + tx * 4 + j;
            g_T[row * UNITS + col] = acc[i][j] + b0[col];
        }
    }
}

// ---------------------------------------------------------------------------
// transpose + convert weights: g_W[m][n*512+k] = fp16(W[k*512+n])
// ---------------------------------------------------------------------------
__global__ void __launch_bounds__(256)
conv_weights(const float* __restrict__ a0, const float* __restrict__ a1,
             const float* __restrict__ a2, const float* __restrict__ a3,
             const float* __restrict__ a4)
{
    int i = blockIdx.x * 256 + threadIdx.x;   // i = k*512+n
    int k = i >> 9, n = i & 511;
    const float* src[5] = {a0, a1, a2, a3, a4};
    #pragma unroll
    for (int m = 0; m < 5; ++m)
        g_W[m][n * UNITS + k] = __float2half_rn(src[m][i]);
}

__global__ void init_states()
{
    int i = blockIdx.x * blockDim.x + threadIdx.x;
    const __half z = __float2half(0.0f);
    #pragma unroll
    for (int l = 0; l < 3; ++l)
        g_s[l][0][i] = z;
    if (i < 16) g_bar[i] = 0;
}

// ---------------------------------------------------------------------------
// stage loader: A (128 x 128) + B (64 x 128) fp16, two 64-col halves each,
// SW128 swizzled 128B rows. One commit_group per stage.
// ---------------------------------------------------------------------------
__device__ __forceinline__ void load_stage(uint32_t base,
    const __half* __restrict__ A, const __half* __restrict__ B,
    int m0, int n0, int k0, int tid)
{
    #pragma unroll
    for (int h = 0; h < 2; ++h) {
        const int kh = k0 + h * 64;
        const uint32_t ab = base + h * 16384u;
        const uint32_t bb = base + 32768u + h * 8192u;
        #pragma unroll
        for (int i = 0; i < 4; ++i) {           // A half: 1024 x 16B
            int idx = tid + i * 256;
            int row = idx >> 3, g = idx & 7;
            uint32_t d = swz((uint32_t)(row * 128 + g * 16));
            CP16(ab + d, A + (size_t)(m0 + row) * UNITS + kh + g * 8);
        }
        #pragma unroll
        for (int i = 0; i < 2; ++i) {           // B half: 512 x 16B
            int idx = tid + i * 256;
            int row = idx >> 3, g = idx & 7;
            uint32_t d = swz((uint32_t)(row * 128 + g * 16));
            CP16(bb + d, B + (size_t)(n0 + row) * UNITS + kh + g * 8);
        }
    }
    asm volatile("cp.async.commit_group;" ::: "memory");
}

// ---------------------------------------------------------------------------
// persistent RNN kernel: grid (8 n, 16 m) = 128 co-resident CTAs.
// Each CTA owns C tile [m0:m0+128) x [n0:n0+64) for the whole sequence.
// The 8 CTAs sharing an m-group sync via a monotonic atomic barrier.
// ---------------------------------------------------------------------------
__global__ void __launch_bounds__(256)
rnn_persistent(const int* __restrict__ tokens,
               const float* __restrict__ b1, const float* __restrict__ b2)
{
    extern __shared__ __align__(1024) char smem[];
    const uint32_t sb = smem_u32(smem);
    const int tid = threadIdx.x, wid = tid >> 5, lane = tid & 31;
    const int n0 = blockIdx.x * 64, m0 = blockIdx.y * 128;
    const int grp = blockIdx.y;

    // warp layout: 4 m-warps x 2 n-warps; warp tile 32x32
    const int wm = (wid & 3) * 32;
    const int wn = (wid >> 2) * 32;
    // ldmatrix lane decode (within a 64-col swizzled half)
    const int sel = lane >> 3, rowin = lane & 7;
    const int a_row  = wm + (sel & 1) * 8 + rowin;
    const int a_colb = (sel >> 1) * 16;
    const int b_row  = wn + (sel >> 1) * 8 + rowin;
    const int b_colb = (sel & 1) * 16;
    const int grpq = lane >> 2, qd = (lane & 3) * 2;  // epilogue decode

    int bidx = 0;   // barrier instance counter (same in all threads)

    for (int t = 0; t < SEQ; ++t) {
        const int p = t & 1;
        #pragma unroll 1
        for (int layer = 0; layer < 3; ++layer) {
            const __half *A0, *B0, *A1, *B1;
            int nmat;
            const float* bias;
            if (layer == 0) {
                nmat = 1; bias = nullptr;
                A0 = g_s[0][p];  B0 = g_W[0];  A1 = A0;  B1 = B0;
            } else {
                nmat = 2;
                int wx = (layer == 1) ? 1 : 3;
                bias = (layer == 1) ? b1 : b2;
                A0 = g_s[layer - 1][p ^ 1];  B0 = g_W[wx];
                A1 = g_s[layer][p];          B1 = g_W[wx + 1];
            }
            __half* outp = g_s[layer][p ^ 1];
            const __half* Asrc[2] = {A0, A1};
            const __half* Bsrc[2] = {B0, B1};
            const int NC = nmat * 4;   // K-128 stages

            float acc[2][4][4] = {};

            // prime stages 0,1 (both belong to mat 0: k=0,128)
            load_stage(sb + 0 * STAGE, A0, B0, m0, n0, 0, tid);
            load_stage(sb + 1 * STAGE, A0, B0, m0, n0, 128, tid);

            for (int c = 0; c < NC; ++c) {
                asm volatile("cp.async.wait_group 1;" ::: "memory");
                __syncthreads();

                const int nc = c + 2;
                if (nc < NC) {
                    load_stage(sb + (nc % NSTAGE) * STAGE,
                               Asrc[nc >> 2], Bsrc[nc >> 2],
                               m0, n0, (nc & 3) * 128, tid);
                } else {
                    asm volatile("cp.async.commit_group;" ::: "memory");
                }

                const uint32_t stb = sb + (uint32_t)(c % NSTAGE) * STAGE;
                #pragma unroll
                for (int h = 0; h < 2; ++h) {
                    const uint32_t Ab = stb + h * 16384u;
                    const uint32_t Bb = stb + 32768u + h * 8192u;
                    #pragma unroll
                    for (int ks = 0; ks < 4; ++ks) {
                        uint32_t a[2][4], b[2][4];
                        #pragma unroll
                        for (int mt = 0; mt < 2; ++mt) {
                            uint32_t off = swz((uint32_t)((a_row + mt * 16) * 128 + a_colb + ks * 32));
                            ldsm4(a[mt], Ab + off);
                        }
                        #pragma unroll
                        for (int bt = 0; bt < 2; ++bt) {
                            uint32_t off = swz((uint32_t)((b_row + bt * 16) * 128 + b_colb + ks * 32));
                            ldsm4(b[bt], Bb + off);
                        }
                        #pragma unroll
                        for (int mt = 0; mt < 2; ++mt)
                            #pragma unroll
                            for (int j = 0; j < 4; ++j)
                                mma16816(acc[mt][j], a[mt], &b[j >> 1][(j & 1) * 2]);
                    }
                }
            }

            // ---- epilogue: add T/bias, tanh, fp16 store ----
            #pragma unroll
            for (int mt = 0; mt < 2; ++mt) {
                const int r0 = m0 + wm + mt * 16 + grpq;
                const int r1 = r0 + 8;
                const float *t0, *t1;
                if (layer == 0) {
                    t0 = g_T + (size_t)tokens[(size_t)r0 * SEQ + t] * UNITS;
                    t1 = g_T + (size_t)tokens[(size_t)r1 * SEQ + t] * UNITS;
                } else {
                    t0 = bias; t1 = bias;
                }
                #pragma unroll
                for (int j = 0; j < 4; ++j) {
                    const int c = n0 + wn + j * 8 + qd;
                    float2 ad0 = *(const float2*)(t0 + c);
                    float2 ad1 = *(const float2*)(t1 + c);
                    __half2 p0 = __floats2half2_rn(fast_tanh(acc[mt][j][0] + ad0.x),
                                                   fast_tanh(acc[mt][j][1] + ad0.y));
                    __half2 p1 = __floats2half2_rn(fast_tanh(acc[mt][j][2] + ad1.x),
                                                   fast_tanh(acc[mt][j][3] + ad1.y));
                    *reinterpret_cast<__half2*>(outp + (size_t)r0 * UNITS + c) = p0;
                    *reinterpret_cast<__half2*>(outp + (size_t)r1 * UNITS + c) = p1;
                }
            }

            // ---- m-group barrier (8 CTAs), monotonic counter ----
            ++bidx;
            __syncthreads();
            if (tid == 0) {
                __threadfence();
                atomicAdd(&g_bar[grp], 1);
                const int target = 8 * bidx;
                unsigned ns = 8;
                for (;;) {
                    int v;
                    asm volatile("ld.acquire.gpu.s32 %0, [%1];"
                                 : "=r"(v) : "l"(&g_bar[grp]));
                    if (v >= target) break;
                    __nanosleep(ns);
                    if (ns < 128) ns <<= 1;
                }
            }
            __syncthreads();
        }
    }
}

// ---------------------------------------------------------------------------
// head: out[b] = sigmoid( s2[b,:] . Wout + bout )
// ---------------------------------------------------------------------------
__global__ void __launch_bounds__(256)
head_kernel(const float* __restrict__ Wout, const float* __restrict__ bout,
            float* __restrict__ out)
{
    const __half* s2 = g_s[2][0];   // SEQ even -> final state in phase 0
    int row  = blockIdx.x * 8 + (threadIdx.x >> 5);
    int lane = threadIdx.x & 31;
    float sum = 0.0f;
    #pragma unroll 4
    for (int k = lane; k < UNITS; k += 32)
        sum += __half2float(s2[(size_t)row * UNITS + k]) * Wout[k];
    #pragma unroll
    for (int o = 16; o; o >>= 1)
        sum += __shfl_xor_sync(0xFFFFFFFFu, sum, o);
    if (lane == 0) {
        float logit = sum + bout[0];
        out[row] = __fdividef(1.0f, 1.0f + __expf(-logit));
    }
}

// ---------------------------------------------------------------------------
extern "C" void kernel_launch(void* const* d_in, const int* in_sizes, int n_in,
                              void* d_out, int out_size)
{
    const int*   tokens = (const int*)  d_in[0];
    const float* emb    = (const float*)d_in[1];
    const float* Wx0    = (const float*)d_in[2];
    const float* Wh0    = (const float*)d_in[3];
    const float* b0     = (const float*)d_in[4];
    const float* Wx1    = (const float*)d_in[5];
    const float* Wh1    = (const float*)d_in[6];
    const float* b1     = (const float*)d_in[7];
    const float* Wx2    = (const float*)d_in[8];
    const float* Wh2    = (const float*)d_in[9];
    const float* b2     = (const float*)d_in[10];
    const float* Wout   = (const float*)d_in[11];
    const float* bout   = (const float*)d_in[12];
    float* out = (float*)d_out;

    cudaFuncSetAttribute(rnn_persistent, cudaFuncAttributeMaxDynamicSharedMemorySize,
                         SMEM_BYTES);

    // prologue
    xproj_kernel<<<dim3((VOCAB + 63) / 64, UNITS / 64), 256>>>(emb, Wx0, b0);
    conv_weights<<<(UNITS * UNITS) / 256, 256>>>(Wh0, Wx1, Wh1, Wx2, Wh2);
    init_states<<<(BATCH * UNITS) / 256, 256>>>();

    // the whole 80x3 recurrence in one persistent launch
    dim3 grid(UNITS / 64, BATCH / 128);   // (8 n, 16 m) = 128 CTAs, 1/SM
    rnn_persistent<<<grid, 256, SMEM_BYTES>>>(tokens, b1, b2);

    head_kernel<<<BATCH / 8, 256>>>(Wout, bout, out);
}